// round 6
// baseline (speedup 1.0000x reference)
#include <cuda_runtime.h>
#include <cstdint>

#define XS_STRIDE 132   // words: 128 + 4 pad — conflict-free ldmatrix
#define WS_STRIDE 136   // words: 128 + 8 pad — conflict-free LDS.128 B loads

// smem byte offsets
#define OFF_A   0         // X tile / ctx: 128 x 132 tf32 words (67584 B)
#define OFF_B0  67584     // W buffer 0:   128 x 136 words (69632 B)
#define OFF_B1  137216    // W buffer 1:   128 x 136 words (69632 B)
#define OFF_MS  206848    // 128 mask words (512 B)
#define SMEM_BYTES 207360

static __device__ __forceinline__ uint32_t f2tf(float f) {
    uint32_t r; asm("cvt.rna.tf32.f32 %0, %1;" : "=r"(r) : "f"(f)); return r;
}

static __device__ __forceinline__ void mma_tf32(float* d,
        uint32_t a0, uint32_t a1, uint32_t a2, uint32_t a3,
        uint32_t b0, uint32_t b1) {
    asm volatile(
        "mma.sync.aligned.m16n8k8.row.col.f32.tf32.tf32.f32 "
        "{%0,%1,%2,%3}, {%4,%5,%6,%7}, {%8,%9}, {%0,%1,%2,%3};\n"
        : "+f"(d[0]), "+f"(d[1]), "+f"(d[2]), "+f"(d[3])
        : "r"(a0), "r"(a1), "r"(a2), "r"(a3), "r"(b0), "r"(b1));
}

static __device__ __forceinline__ void ldsm_x4(uint32_t& r0, uint32_t& r1,
        uint32_t& r2, uint32_t& r3, uint32_t saddr) {
    asm volatile("ldmatrix.sync.aligned.m8n8.x4.shared.b16 {%0,%1,%2,%3}, [%4];"
                 : "=r"(r0), "=r"(r1), "=r"(r2), "=r"(r3) : "r"(saddr));
}

__global__ __launch_bounds__(512, 1)
void laa_kernel(const float* __restrict__ x, const uint32_t* __restrict__ mask,
                const float* __restrict__ Wq, const float* __restrict__ bq,
                const float* __restrict__ Wk, const float* __restrict__ bk,
                const float* __restrict__ Wv, const float* __restrict__ bv,
                const float* __restrict__ Wo, const float* __restrict__ bo,
                float* __restrict__ out)
{
    extern __shared__ char smem[];
    uint32_t* Xs    = (uint32_t*)(smem + OFF_A);
    uint32_t* Bs0   = (uint32_t*)(smem + OFF_B0);
    uint32_t* Bs1   = (uint32_t*)(smem + OFF_B1);
    uint32_t* maskS = (uint32_t*)(smem + OFF_MS);

    const int tid  = threadIdx.x;
    const int lane = tid & 31;
    const int w    = tid >> 5;     // 0..15
    const int gid  = lane >> 2;    // 0..7
    const int tig  = lane & 3;     // 0..3
    const int wm   = w >> 2;       // row group: rows 32*wm..
    const int wn   = w & 3;        // col slab = head wn
    const int row0 = blockIdx.x * 128;

    // ---- stage X tile (128x128 f32 -> tf32) ----
    #pragma unroll
    for (int i = 0; i < 8; i++) {
        int fi = tid + i * 512;              // 0..4095 float4 slots
        int r = fi >> 5, c4 = fi & 31;
        float4 v = *(const float4*)(x + (size_t)(row0 + r) * 128 + c4 * 4);
        uint4 u; u.x = f2tf(v.x); u.y = f2tf(v.y); u.z = f2tf(v.z); u.w = f2tf(v.w);
        *(uint4*)(Xs + r * XS_STRIDE + c4 * 4) = u;
    }
    // ---- stage W with n-permutation: within each 32-col slab, col c stored
    //      at word (c&7)*4 + (c>>3); a fragment's 4 cols become one LDS.128 ----
    const int ws_s = lane >> 3;   // slab 0..3
    const int ws_j = lane & 7;    // within-slab group
    auto stageW = [&](const float* __restrict__ W, uint32_t* Ws) {
        #pragma unroll
        for (int i = 0; i < 8; i++) {
            int k = w * 8 + i;               // row 0..127
            const float* src = W + k * 128 + ws_s * 32 + ws_j;
            float w0 = __ldg(src);
            float w1 = __ldg(src + 8);
            float w2 = __ldg(src + 16);
            float w3 = __ldg(src + 24);
            uint4 u; u.x = f2tf(w0); u.y = f2tf(w1); u.z = f2tf(w2); u.w = f2tf(w3);
            *(uint4*)(Ws + k * WS_STRIDE + ws_s * 32 + ws_j * 4) = u;
        }
    };
    stageW(Wq, Bs0);
    stageW(Wk, Bs1);
    if (tid < 128) maskS[tid] = mask[row0 + tid];
    __syncthreads();

    // ldmatrix bases for the two 16-row m-fragments of this warp's 32-row slab
    const int a_row = wm * 32 + (lane & 15);
    const uint32_t a_base0 =
        (uint32_t)__cvta_generic_to_shared(Xs + a_row * XS_STRIDE + ((lane >> 4) & 1) * 4);
    const uint32_t a_base1 = a_base0 + 16 * XS_STRIDE * 4;

    const int colb = wn * 32 + 2 * tig;       // acc cols (colb, colb+1) + n*8
    const uint32_t boff = (uint32_t)(wn * 32 + gid * 4);

    auto bias_init = [&](float acc[2][4][4], const float* __restrict__ bias) {
        #pragma unroll
        for (int n = 0; n < 4; n++) {
            float2 bb = __ldg((const float2*)(bias + colb + n * 8));
            #pragma unroll
            for (int mf = 0; mf < 2; mf++) {
                acc[mf][n][0] = bb.x; acc[mf][n][1] = bb.y;
                acc[mf][n][2] = bb.x; acc[mf][n][3] = bb.y;
            }
        }
    };

    // single GEMM: acc += Xs(128x128) @ Ws ; warp tile 32x32; B via LDS.128
    auto gemm = [&](float acc[2][4][4], const uint32_t* Ws) {
        #pragma unroll
        for (int kk = 0; kk < 16; kk++) {
            const int k0 = kk * 8;
            uint32_t a0[2], a1[2], a2[2], a3[2];
            ldsm_x4(a0[0], a1[0], a2[0], a3[0], a_base0 + (uint32_t)(k0 * 4));
            ldsm_x4(a0[1], a1[1], a2[1], a3[1], a_base1 + (uint32_t)(k0 * 4));
            const uint32_t* bp = Ws + (k0 + tig) * WS_STRIDE + boff;
            uint4 b0 = *(const uint4*)bp;
            uint4 b1 = *(const uint4*)(bp + 4 * WS_STRIDE);
            #pragma unroll
            for (int mf = 0; mf < 2; mf++) {
                mma_tf32(acc[mf][0], a0[mf], a1[mf], a2[mf], a3[mf], b0.x, b1.x);
                mma_tf32(acc[mf][1], a0[mf], a1[mf], a2[mf], a3[mf], b0.y, b1.y);
                mma_tf32(acc[mf][2], a0[mf], a1[mf], a2[mf], a3[mf], b0.z, b1.z);
                mma_tf32(acc[mf][3], a0[mf], a1[mf], a2[mf], a3[mf], b0.w, b1.w);
            }
        }
    };

    float P[2][2][4];     // attention weights per (mf, half, key atom)
    float rv[2][2];       // residue-valid flag per (mf, half)
    {
        // ---- Q, K GEMMs (separate loops — keeps register pressure bounded) ----
        float Qa[2][4][4], Ka[2][4][4];
        bias_init(Qa, bq);
        gemm(Qa, Bs0);
        bias_init(Ka, bk);
        gemm(Ka, Bs1);

        // ---- scores + softmax, all in registers via shuffles ----
        #pragma unroll
        for (int mf = 0; mf < 2; mf++) {
            #pragma unroll
            for (int half = 0; half < 2; half++) {
                const int rowg = wm * 32 + mf * 16 + half * 8 + gid;
                const int rb   = rowg & ~3;
                float vb[4], sc[4];
                #pragma unroll
                for (int e = 0; e < 4; e++)
                    vb[e] = (maskS[rb | e] != 0u) ? 1.f : 0.f;
                #pragma unroll
                for (int e = 0; e < 4; e++) {
                    const int src = (lane & ~12) | (e << 2);
                    float s = 0.f;
                    #pragma unroll
                    for (int n = 0; n < 4; n++) {
                        #pragma unroll
                        for (int dj = 0; dj < 2; dj++) {
                            int j = half * 2 + dj;
                            s = fmaf(Qa[mf][n][j],
                                     __shfl_sync(0xffffffffu, Ka[mf][n][j], src), s);
                        }
                    }
                    s += __shfl_xor_sync(0xffffffffu, s, 1);
                    s += __shfl_xor_sync(0xffffffffu, s, 2);
                    sc[e] = (vb[e] > 0.f) ? s * 0.17677669529663687f : -1e30f;
                }
                float mx = fmaxf(fmaxf(sc[0], sc[1]), fmaxf(sc[2], sc[3]));
                float ps = 0.f, pe[4];
                #pragma unroll
                for (int e = 0; e < 4; e++) {
                    pe[e] = (vb[e] > 0.f) ? __expf(sc[e] - mx) : 0.f;
                    ps += pe[e];
                }
                float any = vb[0] + vb[1] + vb[2] + vb[3];
                float inv = (any > 0.f) ? (1.f / ps) : 0.f;
                rv[mf][half] = (any > 0.f) ? 1.f : 0.f;
                #pragma unroll
                for (int e = 0; e < 4; e++) P[mf][half][e] = pe[e] * inv;
            }
        }
    }   // Qa, Ka dead

    __syncthreads();            // all warps done with Bs0/Bs1
    stageW(Wv, Bs0);
    stageW(Wo, Bs1);
    __syncthreads();

    // ---- V GEMM + P·V (registers) ----
    float cx[2][4][4];
    {
        float Va[2][4][4];
        bias_init(Va, bv);
        gemm(Va, Bs0);
        #pragma unroll
        for (int mf = 0; mf < 2; mf++)
            #pragma unroll
            for (int n = 0; n < 4; n++)
                #pragma unroll
                for (int j = 0; j < 4; j++) cx[mf][n][j] = 0.f;
        #pragma unroll
        for (int mf = 0; mf < 2; mf++) {
            #pragma unroll
            for (int half = 0; half < 2; half++) {
                #pragma unroll
                for (int e = 0; e < 4; e++) {
                    const int src = (lane & ~12) | (e << 2);
                    const float pw = P[mf][half][e];
                    #pragma unroll
                    for (int n = 0; n < 4; n++) {
                        #pragma unroll
                        for (int dj = 0; dj < 2; dj++) {
                            int j = half * 2 + dj;
                            cx[mf][n][j] = fmaf(pw,
                                __shfl_sync(0xffffffffu, Va[mf][n][j], src),
                                cx[mf][n][j]);
                        }
                    }
                }
            }
        }
    }   // Va dead

    __syncthreads();            // all warps done reading Xs (V GEMM)

    // ---- ctx -> Xs (tf32), rows rowg, cols = this head's slab ----
    #pragma unroll
    for (int mf = 0; mf < 2; mf++) {
        #pragma unroll
        for (int half = 0; half < 2; half++) {
            const int rowg = wm * 32 + mf * 16 + half * 8 + gid;
            #pragma unroll
            for (int n = 0; n < 4; n++) {
                uint2 u;
                u.x = f2tf(cx[mf][n][half * 2 + 0]);
                u.y = f2tf(cx[mf][n][half * 2 + 1]);
                *(uint2*)(Xs + rowg * XS_STRIDE + colb + n * 8) = u;
            }
        }
    }
    __syncthreads();

    // ---- O GEMM + residue zeroing -> global ----
    {
        float Oa[2][4][4];
        bias_init(Oa, bo);
        gemm(Oa, Bs1);
        #pragma unroll
        for (int mf = 0; mf < 2; mf++) {
            #pragma unroll
            for (int half = 0; half < 2; half++) {
                const int rowg = wm * 32 + mf * 16 + half * 8 + gid;
                const float r = rv[mf][half];
                #pragma unroll
                for (int n = 0; n < 4; n++) {
                    float2 o;
                    o.x = Oa[mf][n][half * 2 + 0] * r;
                    o.y = Oa[mf][n][half * 2 + 1] * r;
                    *(float2*)(out + (size_t)(row0 + rowg) * 128 + colb + n * 8) = o;
                }
            }
        }
    }
}

extern "C" void kernel_launch(void* const* d_in, const int* in_sizes, int n_in,
                              void* d_out, int out_size)
{
    const float*    x    = (const float*)d_in[0];
    const uint32_t* mask = (const uint32_t*)d_in[1];
    const float*    Wq   = (const float*)d_in[2];
    const float*    bq   = (const float*)d_in[3];
    const float*    Wk   = (const float*)d_in[4];
    const float*    bk   = (const float*)d_in[5];
    const float*    Wv   = (const float*)d_in[6];
    const float*    bv   = (const float*)d_in[7];
    const float*    Wo   = (const float*)d_in[8];
    const float*    bo   = (const float*)d_in[9];
    float* out = (float*)d_out;

    const int rows = in_sizes[0] / 128;   // 131072
    const int grid = rows / 128;          // 1024

    cudaFuncSetAttribute(laa_kernel, cudaFuncAttributeMaxDynamicSharedMemorySize, SMEM_BYTES);
    laa_kernel<<<grid, 512, SMEM_BYTES>>>(x, mask, Wq, bq, Wk, bk, Wv, bv, Wo, bo, out);
}

// round 7
// speedup vs baseline: 1.1525x; 1.1525x over previous
#include <cuda_runtime.h>
#include <cstdint>

#define XS_STRIDE 132   // words: 128 + 4 pad — conflict-free ldmatrix
#define WS_STRIDE 136   // words: 128 + 8 pad — conflict-free scalar B loads

// smem byte offsets (per CTA)
#define OFF_A   0         // X tile / ctx: 64 x 132 words (33792 B)
#define OFF_B   33792     // W buffer: 128 x 136 words (69632 B)
#define OFF_MS  103424    // 64 mask words (256 B)
#define SMEM_BYTES 103680 // 2 CTAs/SM: 207360 <= 228 KB

static __device__ __forceinline__ uint32_t f2tf(float f) {
    uint32_t r; asm("cvt.rna.tf32.f32 %0, %1;" : "=r"(r) : "f"(f)); return r;
}

static __device__ __forceinline__ void mma_tf32(float* d,
        uint32_t a0, uint32_t a1, uint32_t a2, uint32_t a3,
        uint32_t b0, uint32_t b1) {
    asm volatile(
        "mma.sync.aligned.m16n8k8.row.col.f32.tf32.tf32.f32 "
        "{%0,%1,%2,%3}, {%4,%5,%6,%7}, {%8,%9}, {%0,%1,%2,%3};\n"
        : "+f"(d[0]), "+f"(d[1]), "+f"(d[2]), "+f"(d[3])
        : "r"(a0), "r"(a1), "r"(a2), "r"(a3), "r"(b0), "r"(b1));
}

static __device__ __forceinline__ void ldsm_x4(uint32_t& r0, uint32_t& r1,
        uint32_t& r2, uint32_t& r3, uint32_t saddr) {
    asm volatile("ldmatrix.sync.aligned.m8n8.x4.shared.b16 {%0,%1,%2,%3}, [%4];"
                 : "=r"(r0), "=r"(r1), "=r"(r2), "=r"(r3) : "r"(saddr));
}

__global__ __launch_bounds__(256, 2)
void laa_kernel(const float* __restrict__ x, const uint32_t* __restrict__ mask,
                const float* __restrict__ Wq, const float* __restrict__ bq,
                const float* __restrict__ Wk, const float* __restrict__ bk,
                const float* __restrict__ Wv, const float* __restrict__ bv,
                const float* __restrict__ Wo, const float* __restrict__ bo,
                float* __restrict__ out)
{
    extern __shared__ char smem[];
    uint32_t* Xs    = (uint32_t*)(smem + OFF_A);
    uint32_t* Bs    = (uint32_t*)(smem + OFF_B);
    uint32_t* maskS = (uint32_t*)(smem + OFF_MS);

    const int tid  = threadIdx.x;
    const int lane = tid & 31;
    const int w    = tid >> 5;     // 0..7
    const int gid  = lane >> 2;    // 0..7
    const int tig  = lane & 3;     // 0..3
    const int wm   = w >> 2;       // 0..1: rows 32*wm..
    const int wn   = w & 3;        // col slab = head wn
    const int row0 = blockIdx.x * 64;

    // ---- stage X tile (64x128 f32 -> tf32) ----
    #pragma unroll
    for (int i = 0; i < 8; i++) {
        int fi = tid + i * 256;              // 0..2047 float4 slots
        int r = fi >> 5, c4 = fi & 31;
        float4 v = *(const float4*)(x + (size_t)(row0 + r) * 128 + c4 * 4);
        uint4 u; u.x = f2tf(v.x); u.y = f2tf(v.y); u.z = f2tf(v.z); u.w = f2tf(v.w);
        *(uint4*)(Xs + r * XS_STRIDE + c4 * 4) = u;
    }
    // ---- stage W (row-major k x n, f32 -> tf32) — R4-proven layout ----
    auto stageW = [&](const float* __restrict__ W) {
        #pragma unroll
        for (int i = 0; i < 16; i++) {
            int fi = tid + i * 256;          // 0..4095 float4 slots
            int r = fi >> 5, c4 = fi & 31;
            float4 v = *(const float4*)(W + r * 128 + c4 * 4);
            uint4 u; u.x = f2tf(v.x); u.y = f2tf(v.y); u.z = f2tf(v.z); u.w = f2tf(v.w);
            *(uint4*)(Bs + r * WS_STRIDE + c4 * 4) = u;
        }
    };
    stageW(Wq);
    if (tid < 64) maskS[tid] = mask[row0 + tid];
    __syncthreads();

    // ldmatrix bases for the two 16-row m-fragments of this warp's 32-row slab
    const int a_row = wm * 32 + (lane & 15);
    const uint32_t a_base0 =
        (uint32_t)__cvta_generic_to_shared(Xs + a_row * XS_STRIDE + ((lane >> 4) & 1) * 4);
    const uint32_t a_base1 = a_base0 + 16 * XS_STRIDE * 4;

    const int colb = wn * 32 + 2 * tig;       // acc cols (colb, colb+1) + n*8

    // GEMM: acc = Xs(64x128) @ Bs(128x128); warp tile 32x32 — R4-proven inner loop
    auto gemm = [&](float acc[2][4][4]) {
        #pragma unroll
        for (int mf = 0; mf < 2; mf++)
            #pragma unroll
            for (int n = 0; n < 4; n++)
                #pragma unroll
                for (int j = 0; j < 4; j++) acc[mf][n][j] = 0.f;
        #pragma unroll
        for (int kk = 0; kk < 16; kk++) {
            const int k0 = kk * 8;
            uint32_t a0[2], a1[2], a2[2], a3[2];
            ldsm_x4(a0[0], a1[0], a2[0], a3[0], a_base0 + (uint32_t)(k0 * 4));
            ldsm_x4(a0[1], a1[1], a2[1], a3[1], a_base1 + (uint32_t)(k0 * 4));
            const uint32_t* bp = Bs + (k0 + tig) * WS_STRIDE + wn * 32 + gid;
            uint32_t b[4][2];
            #pragma unroll
            for (int n = 0; n < 4; n++) {
                b[n][0] = bp[n * 8];
                b[n][1] = bp[4 * WS_STRIDE + n * 8];
            }
            #pragma unroll
            for (int mf = 0; mf < 2; mf++)
                #pragma unroll
                for (int n = 0; n < 4; n++)
                    mma_tf32(acc[mf][n], a0[mf], a1[mf], a2[mf], a3[mf],
                             b[n][0], b[n][1]);
        }
    };

    auto bias_add = [&](float acc[2][4][4], const float* __restrict__ bias) {
        #pragma unroll
        for (int n = 0; n < 4; n++) {
            float2 bb = __ldg((const float2*)(bias + colb + n * 8));
            #pragma unroll
            for (int mf = 0; mf < 2; mf++) {
                acc[mf][n][0] += bb.x; acc[mf][n][1] += bb.y;
                acc[mf][n][2] += bb.x; acc[mf][n][3] += bb.y;
            }
        }
    };

    float P[2][2][4];     // attention weights per (mf, half, key atom)
    float rv[2][2];       // residue-valid flag per (mf, half)
    {
        // ---- Q GEMM ----
        float Qa[2][4][4];
        gemm(Qa);
        bias_add(Qa, bq);
        __syncthreads();                     // done reading Bs
        stageW(Wk);
        __syncthreads();

        // ---- K GEMM ----
        float Ka[2][4][4];
        gemm(Ka);
        bias_add(Ka, bk);

        // ---- scores + softmax, registers + shuffles ----
        #pragma unroll
        for (int mf = 0; mf < 2; mf++) {
            #pragma unroll
            for (int half = 0; half < 2; half++) {
                const int rowg = wm * 32 + mf * 16 + half * 8 + gid;
                const int rb   = rowg & ~3;
                float vb[4], sc[4];
                #pragma unroll
                for (int e = 0; e < 4; e++)
                    vb[e] = (maskS[rb | e] != 0u) ? 1.f : 0.f;
                #pragma unroll
                for (int e = 0; e < 4; e++) {
                    const int src = (lane & ~12) | (e << 2);
                    float s = 0.f;
                    #pragma unroll
                    for (int n = 0; n < 4; n++) {
                        #pragma unroll
                        for (int dj = 0; dj < 2; dj++) {
                            int j = half * 2 + dj;
                            s = fmaf(Qa[mf][n][j],
                                     __shfl_sync(0xffffffffu, Ka[mf][n][j], src), s);
                        }
                    }
                    s += __shfl_xor_sync(0xffffffffu, s, 1);
                    s += __shfl_xor_sync(0xffffffffu, s, 2);
                    sc[e] = (vb[e] > 0.f) ? s * 0.17677669529663687f : -1e30f;
                }
                float mx = fmaxf(fmaxf(sc[0], sc[1]), fmaxf(sc[2], sc[3]));
                float ps = 0.f, pe[4];
                #pragma unroll
                for (int e = 0; e < 4; e++) {
                    pe[e] = (vb[e] > 0.f) ? __expf(sc[e] - mx) : 0.f;
                    ps += pe[e];
                }
                float any = vb[0] + vb[1] + vb[2] + vb[3];
                float inv = (any > 0.f) ? (1.f / ps) : 0.f;
                rv[mf][half] = (any > 0.f) ? 1.f : 0.f;
                #pragma unroll
                for (int e = 0; e < 4; e++) P[mf][half][e] = pe[e] * inv;
            }
        }
    }   // Qa, Ka dead

    __syncthreads();            // done reading Bs (K GEMM)
    stageW(Wv);
    __syncthreads();

    // ---- V GEMM + P·V (registers) ----
    float cx[2][4][4];
    {
        float Va[2][4][4];
        gemm(Va);
        bias_add(Va, bv);
        #pragma unroll
        for (int mf = 0; mf < 2; mf++)
            #pragma unroll
            for (int n = 0; n < 4; n++)
                #pragma unroll
                for (int j = 0; j < 4; j++) cx[mf][n][j] = 0.f;
        #pragma unroll
        for (int mf = 0; mf < 2; mf++) {
            #pragma unroll
            for (int half = 0; half < 2; half++) {
                #pragma unroll
                for (int e = 0; e < 4; e++) {
                    const int src = (lane & ~12) | (e << 2);
                    const float pw = P[mf][half][e];
                    #pragma unroll
                    for (int n = 0; n < 4; n++) {
                        #pragma unroll
                        for (int dj = 0; dj < 2; dj++) {
                            int j = half * 2 + dj;
                            cx[mf][n][j] = fmaf(pw,
                                __shfl_sync(0xffffffffu, Va[mf][n][j], src),
                                cx[mf][n][j]);
                        }
                    }
                }
            }
        }
    }   // Va dead

    __syncthreads();            // all warps done reading Xs (V GEMM) + Bs

    // ---- ctx -> Xs (tf32) ; stage Wo concurrently ----
    #pragma unroll
    for (int mf = 0; mf < 2; mf++) {
        #pragma unroll
        for (int half = 0; half < 2; half++) {
            const int rowg = wm * 32 + mf * 16 + half * 8 + gid;
            #pragma unroll
            for (int n = 0; n < 4; n++) {
                uint2 u;
                u.x = f2tf(cx[mf][n][half * 2 + 0]);
                u.y = f2tf(cx[mf][n][half * 2 + 1]);
                *(uint2*)(Xs + rowg * XS_STRIDE + colb + n * 8) = u;
            }
        }
    }
    stageW(Wo);
    __syncthreads();

    // ---- O GEMM + bias + residue zeroing -> global ----
    {
        float Oa[2][4][4];
        gemm(Oa);
        bias_add(Oa, bo);
        #pragma unroll
        for (int mf = 0; mf < 2; mf++) {
            #pragma unroll
            for (int half = 0; half < 2; half++) {
                const int rowg = wm * 32 + mf * 16 + half * 8 + gid;
                const float r = rv[mf][half];
                #pragma unroll
                for (int n = 0; n < 4; n++) {
                    float2 o;
                    o.x = Oa[mf][n][half * 2 + 0] * r;
                    o.y = Oa[mf][n][half * 2 + 1] * r;
                    *(float2*)(out + (size_t)(row0 + rowg) * 128 + colb + n * 8) = o;
                }
            }
        }
    }
}

extern "C" void kernel_launch(void* const* d_in, const int* in_sizes, int n_in,
                              void* d_out, int out_size)
{
    const float*    x    = (const float*)d_in[0];
    const uint32_t* mask = (const uint32_t*)d_in[1];
    const float*    Wq   = (const float*)d_in[2];
    const float*    bq   = (const float*)d_in[3];
    const float*    Wk   = (const float*)d_in[4];
    const float*    bk   = (const float*)d_in[5];
    const float*    Wv   = (const float*)d_in[6];
    const float*    bv   = (const float*)d_in[7];
    const float*    Wo   = (const float*)d_in[8];
    const float*    bo   = (const float*)d_in[9];
    float* out = (float*)d_out;

    const int rows = in_sizes[0] / 128;   // 131072
    const int grid = rows / 64;           // 2048

    cudaFuncSetAttribute(laa_kernel, cudaFuncAttributeMaxDynamicSharedMemorySize, SMEM_BYTES);
    laa_kernel<<<grid, 256, SMEM_BYTES>>>(x, mask, Wq, bq, Wk, bk, Wv, bv, Wo, bo, out);
}

// round 8
// speedup vs baseline: 1.3094x; 1.1362x over previous
#include <cuda_runtime.h>
#include <cstdint>

#define XS_STRIDE 132   // words: 128 + 4 pad — conflict-free ldmatrix
#define WS_STRIDE 136   // words: 128 + 8 pad — conflict-free scalar B loads

// smem byte offsets
#define OFF_A   0         // X tile / ctx: 128 x 132 tf32 words (67584 B)
#define OFF_B0  67584     // W buffer 0:   128 x 136 words (69632 B)
#define OFF_B1  137216    // W buffer 1:   128 x 136 words (69632 B)
#define OFF_MS  206848    // 128 mask words (512 B)
#define SMEM_BYTES 207360

static __device__ __forceinline__ uint32_t f2tf(float f) {
    uint32_t r; asm("cvt.rna.tf32.f32 %0, %1;" : "=r"(r) : "f"(f)); return r;
}

static __device__ __forceinline__ void mma_tf32(float* d,
        uint32_t a0, uint32_t a1, uint32_t a2, uint32_t a3,
        uint32_t b0, uint32_t b1) {
    asm volatile(
        "mma.sync.aligned.m16n8k8.row.col.f32.tf32.tf32.f32 "
        "{%0,%1,%2,%3}, {%4,%5,%6,%7}, {%8,%9}, {%0,%1,%2,%3};\n"
        : "+f"(d[0]), "+f"(d[1]), "+f"(d[2]), "+f"(d[3])
        : "r"(a0), "r"(a1), "r"(a2), "r"(a3), "r"(b0), "r"(b1));
}

static __device__ __forceinline__ void ldsm_x4(uint32_t& r0, uint32_t& r1,
        uint32_t& r2, uint32_t& r3, uint32_t saddr) {
    asm volatile("ldmatrix.sync.aligned.m8n8.x4.shared.b16 {%0,%1,%2,%3}, [%4];"
                 : "=r"(r0), "=r"(r1), "=r"(r2), "=r"(r3) : "r"(saddr));
}

#define CP_COMMIT()  asm volatile("cp.async.commit_group;" ::: "memory")
#define CP_WAIT(n)   asm volatile("cp.async.wait_group %0;" :: "n"(n) : "memory")

__global__ __launch_bounds__(512, 1)
void laa_kernel(const float* __restrict__ x, const uint32_t* __restrict__ mask,
                const float* __restrict__ Wq, const float* __restrict__ bq,
                const float* __restrict__ Wk, const float* __restrict__ bk,
                const float* __restrict__ Wv, const float* __restrict__ bv,
                const float* __restrict__ Wo, const float* __restrict__ bo,
                float* __restrict__ out)
{
    extern __shared__ char smem[];
    uint32_t* Xs    = (uint32_t*)(smem + OFF_A);
    uint32_t* Bs0   = (uint32_t*)(smem + OFF_B0);
    uint32_t* Bs1   = (uint32_t*)(smem + OFF_B1);
    uint32_t* maskS = (uint32_t*)(smem + OFF_MS);

    const int tid  = threadIdx.x;
    const int lane = tid & 31;
    const int w    = tid >> 5;     // 0..15
    const int gid  = lane >> 2;    // 0..7
    const int tig  = lane & 3;     // 0..3
    const int wm   = w >> 2;       // row group: rows 32*wm..
    const int wn   = w & 3;        // col slab = head wn
    const int row0 = blockIdx.x * 128;

    // async W copy: W (128x128 f32 row-major) -> Ws, raw f32 (HMMA reads tf32 bits)
    auto cpW = [&](const float* __restrict__ W, uint32_t* Ws) {
        #pragma unroll
        for (int i = 0; i < 8; i++) {
            int fi = tid + i * 512;          // 0..4095 float4 slots
            int r = fi >> 5, c4 = fi & 31;
            uint32_t d = (uint32_t)__cvta_generic_to_shared(Ws + r * WS_STRIDE + c4 * 4);
            asm volatile("cp.async.cg.shared.global [%0], [%1], 16;"
                         :: "r"(d), "l"(W + r * 128 + c4 * 4) : "memory");
        }
    };

    // ---- kick off Wq, Wk copies first (group 0), overlap with X staging ----
    cpW(Wq, Bs0);
    cpW(Wk, Bs1);
    CP_COMMIT();

    // ---- stage X tile (128x128 f32 -> tf32, cvt.rna) ----
    #pragma unroll
    for (int i = 0; i < 8; i++) {
        int fi = tid + i * 512;              // 0..4095 float4 slots
        int r = fi >> 5, c4 = fi & 31;
        float4 v = *(const float4*)(x + (size_t)(row0 + r) * 128 + c4 * 4);
        uint4 u; u.x = f2tf(v.x); u.y = f2tf(v.y); u.z = f2tf(v.z); u.w = f2tf(v.w);
        *(uint4*)(Xs + r * XS_STRIDE + c4 * 4) = u;
    }
    if (tid < 128) maskS[tid] = mask[row0 + tid];
    CP_WAIT(0);
    __syncthreads();

    // ldmatrix bases for the two 16-row m-fragments of this warp's 32-row slab
    const int a_row = wm * 32 + (lane & 15);
    const uint32_t a_base0 =
        (uint32_t)__cvta_generic_to_shared(Xs + a_row * XS_STRIDE + ((lane >> 4) & 1) * 4);
    const uint32_t a_base1 = a_base0 + 16 * XS_STRIDE * 4;

    const int colb = wn * 32 + 2 * tig;       // acc cols (colb, colb+1) + n*8

    // GEMM: acc = Xs(128x128) @ Ws(128x128); warp tile 32x32 (R4-proven)
    auto gemm = [&](float acc[2][4][4], const uint32_t* Ws) {
        #pragma unroll
        for (int mf = 0; mf < 2; mf++)
            #pragma unroll
            for (int n = 0; n < 4; n++)
                #pragma unroll
                for (int j = 0; j < 4; j++) acc[mf][n][j] = 0.f;
        #pragma unroll
        for (int kk = 0; kk < 16; kk++) {
            const int k0 = kk * 8;
            uint32_t a0[2], a1[2], a2[2], a3[2];
            ldsm_x4(a0[0], a1[0], a2[0], a3[0], a_base0 + (uint32_t)(k0 * 4));
            ldsm_x4(a0[1], a1[1], a2[1], a3[1], a_base1 + (uint32_t)(k0 * 4));
            const uint32_t* bp = Ws + (k0 + tig) * WS_STRIDE + wn * 32 + gid;
            uint32_t b[4][2];
            #pragma unroll
            for (int n = 0; n < 4; n++) {
                b[n][0] = bp[n * 8];
                b[n][1] = bp[4 * WS_STRIDE + n * 8];
            }
            #pragma unroll
            for (int mf = 0; mf < 2; mf++)
                #pragma unroll
                for (int n = 0; n < 4; n++)
                    mma_tf32(acc[mf][n], a0[mf], a1[mf], a2[mf], a3[mf],
                             b[n][0], b[n][1]);
        }
    };

    auto bias_add = [&](float acc[2][4][4], const float* __restrict__ bias) {
        #pragma unroll
        for (int n = 0; n < 4; n++) {
            float2 bb = __ldg((const float2*)(bias + colb + n * 8));
            #pragma unroll
            for (int mf = 0; mf < 2; mf++) {
                acc[mf][n][0] += bb.x; acc[mf][n][1] += bb.y;
                acc[mf][n][2] += bb.x; acc[mf][n][3] += bb.y;
            }
        }
    };

    float P[2][2][4];     // attention weights per (mf, half, key atom)
    float rv[2][2];       // residue-valid flag per (mf, half)
    {
        // ---- Q GEMM ----
        float Qa[2][4][4];
        gemm(Qa, Bs0);
        bias_add(Qa, bq);
        __syncthreads();                 // all warps done reading Bs0

        // Wv -> Bs0 flows during K GEMM + softmax (group 1)
        cpW(Wv, Bs0);
        CP_COMMIT();

        // ---- K GEMM ----
        float Ka[2][4][4];
        gemm(Ka, Bs1);
        bias_add(Ka, bk);

        // ---- scores + softmax, registers + shuffles ----
        #pragma unroll
        for (int mf = 0; mf < 2; mf++) {
            #pragma unroll
            for (int half = 0; half < 2; half++) {
                const int rowg = wm * 32 + mf * 16 + half * 8 + gid;
                const int rb   = rowg & ~3;
                float vb[4], sc[4];
                #pragma unroll
                for (int e = 0; e < 4; e++)
                    vb[e] = (maskS[rb | e] != 0u) ? 1.f : 0.f;
                #pragma unroll
                for (int e = 0; e < 4; e++) {
                    const int src = (lane & ~12) | (e << 2);
                    float s = 0.f;
                    #pragma unroll
                    for (int n = 0; n < 4; n++) {
                        #pragma unroll
                        for (int dj = 0; dj < 2; dj++) {
                            int j = half * 2 + dj;
                            s = fmaf(Qa[mf][n][j],
                                     __shfl_sync(0xffffffffu, Ka[mf][n][j], src), s);
                        }
                    }
                    s += __shfl_xor_sync(0xffffffffu, s, 1);
                    s += __shfl_xor_sync(0xffffffffu, s, 2);
                    sc[e] = (vb[e] > 0.f) ? s * 0.17677669529663687f : -1e30f;
                }
                float mx = fmaxf(fmaxf(sc[0], sc[1]), fmaxf(sc[2], sc[3]));
                float ps = 0.f, pe[4];
                #pragma unroll
                for (int e = 0; e < 4; e++) {
                    pe[e] = (vb[e] > 0.f) ? __expf(sc[e] - mx) : 0.f;
                    ps += pe[e];
                }
                float any = vb[0] + vb[1] + vb[2] + vb[3];
                float inv = (any > 0.f) ? (1.f / ps) : 0.f;
                rv[mf][half] = (any > 0.f) ? 1.f : 0.f;
                #pragma unroll
                for (int e = 0; e < 4; e++) P[mf][half][e] = pe[e] * inv;
            }
        }
    }   // Qa, Ka dead

    __syncthreads();                 // all warps done reading Bs1 (K GEMM)

    // Wo -> Bs1 flows during V GEMM + P.V + ctx write (group 2)
    cpW(Wo, Bs1);
    CP_COMMIT();
    CP_WAIT(1);                      // Wv (group 1) arrived
    __syncthreads();                 // Wv visible to all warps

    // ---- V GEMM + P·V (registers) ----
    float cx[2][4][4];
    {
        float Va[2][4][4];
        gemm(Va, Bs0);
        bias_add(Va, bv);
        #pragma unroll
        for (int mf = 0; mf < 2; mf++)
            #pragma unroll
            for (int n = 0; n < 4; n++)
                #pragma unroll
                for (int j = 0; j < 4; j++) cx[mf][n][j] = 0.f;
        #pragma unroll
        for (int mf = 0; mf < 2; mf++) {
            #pragma unroll
            for (int half = 0; half < 2; half++) {
                #pragma unroll
                for (int e = 0; e < 4; e++) {
                    const int src = (lane & ~12) | (e << 2);
                    const float pw = P[mf][half][e];
                    #pragma unroll
                    for (int n = 0; n < 4; n++) {
                        #pragma unroll
                        for (int dj = 0; dj < 2; dj++) {
                            int j = half * 2 + dj;
                            cx[mf][n][j] = fmaf(pw,
                                __shfl_sync(0xffffffffu, Va[mf][n][j], src),
                                cx[mf][n][j]);
                        }
                    }
                }
            }
        }
    }   // Va dead

    __syncthreads();            // all warps done reading Xs (V GEMM)

    // ---- ctx -> Xs (tf32, cvt.rna) ----
    #pragma unroll
    for (int mf = 0; mf < 2; mf++) {
        #pragma unroll
        for (int half = 0; half < 2; half++) {
            const int rowg = wm * 32 + mf * 16 + half * 8 + gid;
            #pragma unroll
            for (int n = 0; n < 4; n++) {
                uint2 u;
                u.x = f2tf(cx[mf][n][half * 2 + 0]);
                u.y = f2tf(cx[mf][n][half * 2 + 1]);
                *(uint2*)(Xs + rowg * XS_STRIDE + colb + n * 8) = u;
            }
        }
    }
    CP_WAIT(0);                 // Wo (group 2) arrived
    __syncthreads();            // ctx + Wo visible

    // ---- O GEMM + bias + residue zeroing -> global ----
    {
        float Oa[2][4][4];
        gemm(Oa, Bs1);
        bias_add(Oa, bo);
        #pragma unroll
        for (int mf = 0; mf < 2; mf++) {
            #pragma unroll
            for (int half = 0; half < 2; half++) {
                const int rowg = wm * 32 + mf * 16 + half * 8 + gid;
                const float r = rv[mf][half];
                #pragma unroll
                for (int n = 0; n < 4; n++) {
                    float2 o;
                    o.x = Oa[mf][n][half * 2 + 0] * r;
                    o.y = Oa[mf][n][half * 2 + 1] * r;
                    *(float2*)(out + (size_t)(row0 + rowg) * 128 + colb + n * 8) = o;
                }
            }
        }
    }
}

extern "C" void kernel_launch(void* const* d_in, const int* in_sizes, int n_in,
                              void* d_out, int out_size)
{
    const float*    x    = (const float*)d_in[0];
    const uint32_t* mask = (const uint32_t*)d_in[1];
    const float*    Wq   = (const float*)d_in[2];
    const float*    bq   = (const float*)d_in[3];
    const float*    Wk   = (const float*)d_in[4];
    const float*    bk   = (const float*)d_in[5];
    const float*    Wv   = (const float*)d_in[6];
    const float*    bv   = (const float*)d_in[7];
    const float*    Wo   = (const float*)d_in[8];
    const float*    bo   = (const float*)d_in[9];
    float* out = (float*)d_out;

    const int rows = in_sizes[0] / 128;   // 131072
    const int grid = rows / 128;          // 1024

    cudaFuncSetAttribute(laa_kernel, cudaFuncAttributeMaxDynamicSharedMemorySize, SMEM_BYTES);
    laa_kernel<<<grid, 512, SMEM_BYTES>>>(x, mask, Wq, bq, Wk, bk, Wv, bv, Wo, bo, out);
}